// round 1
// baseline (speedup 1.0000x reference)
#include <cuda_runtime.h>

// ---------------------------------------------------------------------------
// IMCNN (FAUST) forward pass, fp32 baseline.
// Pipeline:
//   1. normalize signal -> g_x (V,3)
//   2. per layer l in 0..2:
//        a. patch[v,(r,a),c] = sum_i x[bc_idx[v,r,a,i], c] * bc_w[v,r,a,i]
//        b. Brot[(r,a,c),(n,t)] = W_l[t, r, (a+n)%A, c]
//        c. conv = relu(patch @ Brot + b_l[t])        (GEMM M=V,N=800,K=R*A*C)
//        d. AMP (argmax rotation by L2 norm, first-max) + BN -> g_x (V,100)
//   3. out = g_x @ dense_w + dense_b                  (GEMM M=V,N=V,K=100)
// ---------------------------------------------------------------------------

#define V     6890
#define RR    5
#define AA    8
#define NROT  8
#define TT    100
#define CMAX  100
#define NCOLS (NROT * TT)      // 800
#define EPS_BN 1e-3f

// scratch (static device allocations; allowed per harness rules)
__device__ float g_x[V * CMAX];                     // layer activations (V, Cin)
__device__ float g_patch[V * RR * AA * CMAX];       // ~110 MB
__device__ float g_brot[RR * AA * CMAX * NCOLS];    // ~12.8 MB
__device__ float g_conv[V * NCOLS];                 // ~22 MB

// ---------------------------------------------------------------------------
__global__ void k_norm(const float* __restrict__ sig,
                       const float* __restrict__ mean,
                       const float* __restrict__ var) {
    int i = blockIdx.x * blockDim.x + threadIdx.x;
    if (i < V * 3) {
        int c = i % 3;
        g_x[i] = (sig[i] - mean[c]) / sqrtf(var[c]);
    }
}

// patch[p*Cin + c] = sum_i g_x[idx[p,i]*Cin + c] * w[p,i]
__global__ void k_patch(const int* __restrict__ bc_idx,
                        const float* __restrict__ bc_w,
                        int Cin) {
    int i = blockIdx.x * blockDim.x + threadIdx.x;
    int total = V * RR * AA * Cin;
    if (i >= total) return;
    int c = i % Cin;
    int p = i / Cin;
    const int*   idx = bc_idx + p * 3;
    const float* w   = bc_w + p * 3;
    float s = 0.f;
#pragma unroll
    for (int j = 0; j < 3; ++j)
        s += g_x[idx[j] * Cin + c] * w[j];
    g_patch[i] = s;
}

// Brot[k*NCOLS + col], k = (r*AA + a)*Cin + c, col = n*TT + t
// Brot = W[t, r, (a+n)%AA, c]
__global__ void k_brot(const float* __restrict__ W, int Cin) {
    int i = blockIdx.x * blockDim.x + threadIdx.x;
    int K = RR * AA * Cin;
    if (i >= K * NCOLS) return;
    int col = i % NCOLS;
    int k   = i / NCOLS;
    int c  = k % Cin;
    int ra = k / Cin;
    int a  = ra % AA;
    int r  = ra / AA;
    int t  = col % TT;
    int n  = col / TT;
    int a2 = (a + n) & (AA - 1);
    g_brot[i] = W[((t * RR + r) * AA + a2) * Cin + c];
}

// ---------------------------------------------------------------------------
// Tiled fp32 GEMM: C[M,N] = A[M,K] @ B[K,N] + bias[col % bias_mod], opt relu.
// BM=128, BN=64, BK=16; 256 threads; 8x4 micro-tile per thread.
#define BM 128
#define BN 64
#define BK 16

__global__ void __launch_bounds__(256)
k_gemm(const float* __restrict__ A, const float* __restrict__ B,
       const float* __restrict__ bias, float* __restrict__ C,
       int M, int N, int K, int bias_mod, int relu) {
    __shared__ float Asm[BM][BK + 1];   // [m][kk], +1 pad: conflict-free STS/LDS
    __shared__ float Bsm[BK][BN];       // [kk][n], float4 LDS in compute

    int tid = threadIdx.x;
    int tx = tid % 16;          // 0..15 -> 4 cols each
    int ty = tid / 16;          // 0..15 -> 8 rows each
    int row0 = blockIdx.y * BM;
    int col0 = blockIdx.x * BN;

    float acc[8][4];
#pragma unroll
    for (int i = 0; i < 8; ++i)
#pragma unroll
        for (int j = 0; j < 4; ++j) acc[i][j] = 0.f;

    for (int k0 = 0; k0 < K; k0 += BK) {
        // load A tile (BM x BK = 2048 elems): coalesced 16-wide per row
#pragma unroll
        for (int e = tid; e < BM * BK; e += 256) {
            int m  = e / BK;
            int kk = e % BK;
            int gr = row0 + m;
            int gk = k0 + kk;
            Asm[m][kk] = (gr < M && gk < K) ? A[(long)gr * K + gk] : 0.f;
        }
        // load B tile (BK x BN = 1024 elems): fully coalesced
#pragma unroll
        for (int e = tid; e < BK * BN; e += 256) {
            int kk = e / BN;
            int n  = e % BN;
            int gk = k0 + kk;
            int gc = col0 + n;
            Bsm[kk][n] = (gk < K && gc < N) ? B[(long)gk * N + gc] : 0.f;
        }
        __syncthreads();

#pragma unroll
        for (int kk = 0; kk < BK; ++kk) {
            float a[8];
#pragma unroll
            for (int i = 0; i < 8; ++i) a[i] = Asm[ty * 8 + i][kk];
            float4 b4 = *(const float4*)&Bsm[kk][tx * 4];
            float b[4] = {b4.x, b4.y, b4.z, b4.w};
#pragma unroll
            for (int i = 0; i < 8; ++i)
#pragma unroll
                for (int j = 0; j < 4; ++j)
                    acc[i][j] += a[i] * b[j];
        }
        __syncthreads();
    }

#pragma unroll
    for (int i = 0; i < 8; ++i) {
        int r = row0 + ty * 8 + i;
        if (r >= M) continue;
#pragma unroll
        for (int j = 0; j < 4; ++j) {
            int c = col0 + tx * 4 + j;
            if (c >= N) continue;
            float val = acc[i][j] + bias[c % bias_mod];
            if (relu) val = fmaxf(val, 0.f);
            C[(long)r * N + c] = val;
        }
    }
}

// ---------------------------------------------------------------------------
// AngularMaxPooling (first-max over rotations by L2 norm) + BatchNorm.
// One warp per vertex. Reads g_conv (V, 8, 100), writes g_x (V, 100).
__global__ void k_amp_bn(const float* __restrict__ gam,
                         const float* __restrict__ bet,
                         const float* __restrict__ mu,
                         const float* __restrict__ var) {
    int warp = (blockIdx.x * blockDim.x + threadIdx.x) / 32;
    int lane = threadIdx.x & 31;
    if (warp >= V) return;
    const float* row = g_conv + (long)warp * NCOLS;

    float best = -1.0f;
    int bestn = 0;
#pragma unroll
    for (int n = 0; n < NROT; ++n) {
        float s = 0.f;
        for (int t = lane; t < TT; t += 32) {
            float x = row[n * TT + t];
            s += x * x;
        }
#pragma unroll
        for (int off = 16; off > 0; off >>= 1)
            s += __shfl_xor_sync(0xFFFFFFFFu, s, off);
        if (s > best) { best = s; bestn = n; }   // strict > => first max
    }

    for (int t = lane; t < TT; t += 32) {
        float x = row[bestn * TT + t];
        float y = gam[t] * (x - mu[t]) * rsqrtf(var[t] + EPS_BN) + bet[t];
        g_x[warp * TT + t] = y;
    }
}

// ---------------------------------------------------------------------------
extern "C" void kernel_launch(void* const* d_in, const int* in_sizes, int n_in,
                              void* d_out, int out_size) {
    const float* signal = (const float*)d_in[0];
    const int*   bc_idx = (const int*)d_in[1];
    const float* bc_w   = (const float*)d_in[2];
    const float* nmean  = (const float*)d_in[3];
    const float* nvar   = (const float*)d_in[4];
    const float* Ws[3]  = {(const float*)d_in[5], (const float*)d_in[7],
                           (const float*)d_in[9]};
    const float* Bls[3] = {(const float*)d_in[6], (const float*)d_in[8],
                           (const float*)d_in[10]};
    const float* bng = (const float*)d_in[11];
    const float* bnb = (const float*)d_in[12];
    const float* bnm = (const float*)d_in[13];
    const float* bnv = (const float*)d_in[14];
    const float* dw  = (const float*)d_in[15];
    const float* db  = (const float*)d_in[16];
    float* out = (float*)d_out;

    float *pPatch, *pBrot, *pConv, *pX;
    cudaGetSymbolAddress((void**)&pPatch, g_patch);
    cudaGetSymbolAddress((void**)&pBrot,  g_brot);
    cudaGetSymbolAddress((void**)&pConv,  g_conv);
    cudaGetSymbolAddress((void**)&pX,     g_x);

    k_norm<<<(V * 3 + 255) / 256, 256>>>(signal, nmean, nvar);

    int Cin = 3;
    for (int l = 0; l < 3; ++l) {
        int K = RR * AA * Cin;
        int tot = V * RR * AA * Cin;
        k_patch<<<(tot + 255) / 256, 256>>>(bc_idx, bc_w, Cin);
        k_brot<<<(K * NCOLS + 255) / 256, 256>>>(Ws[l], Cin);
        dim3 g((NCOLS + BN - 1) / BN, (V + BM - 1) / BM);
        k_gemm<<<g, 256>>>(pPatch, pBrot, Bls[l], pConv, V, NCOLS, K, TT, 1);
        k_amp_bn<<<(V + 7) / 8, 256>>>(bng + l * TT, bnb + l * TT,
                                       bnm + l * TT, bnv + l * TT);
        Cin = TT;
    }

    dim3 g2((V + BN - 1) / BN, (V + BM - 1) / BM);
    k_gemm<<<g2, 256>>>(pX, dw, db, out, V, V, TT, V, 0);
}

// round 3
// speedup vs baseline: 2.9250x; 2.9250x over previous
#include <cuda_runtime.h>
#include <cuda_bf16.h>
#include <cstdint>

// ---------------------------------------------------------------------------
// IMCNN forward. Tensor path: mma.sync m16n8k16 bf16 (HMMA), bf16x3 split,
// fp32 accumulate. (tcgen05 is unavailable: harness compiles PTX at
// compute_103, which rejects arch-accelerated instructions.)
// ---------------------------------------------------------------------------

#define V      6890
#define RR     5
#define AA     8
#define TT     100
#define NCONV  800
#define KPAD_BIG 4032
#define KPAD_S   128
#define EPS_BN 1e-3f

__device__ float g_x[V * TT];
__device__ float g_conv[V * NCONV];
__device__ __align__(16) __nv_bfloat16 g_phi[(size_t)V * KPAD_BIG];
__device__ __align__(16) __nv_bfloat16 g_plo[(size_t)V * KPAD_BIG];
__device__ __align__(16) __nv_bfloat16 g_bhi[(size_t)NCONV * KPAD_BIG];
__device__ __align__(16) __nv_bfloat16 g_blo[(size_t)NCONV * KPAD_BIG];
__device__ __align__(16) __nv_bfloat16 g_xhi[V * KPAD_S];
__device__ __align__(16) __nv_bfloat16 g_xlo[V * KPAD_S];
__device__ __align__(16) __nv_bfloat16 g_dhi[(size_t)V * KPAD_S];
__device__ __align__(16) __nv_bfloat16 g_dlo[(size_t)V * KPAD_S];

// -------------------- PTX helpers (family-baseline only) --------------------
__device__ __forceinline__ uint32_t smem_u32(const void* p) {
    uint32_t a;
    asm("{ .reg .u64 t; cvta.to.shared.u64 t, %1; cvt.u32.u64 %0, t; }"
        : "=r"(a) : "l"(p));
    return a;
}
#define CP_ASYNC16(dst, src) \
    asm volatile("cp.async.cg.shared.global [%0], [%1], 16;" \
                 :: "r"(dst), "l"(src))
#define CP_COMMIT() asm volatile("cp.async.commit_group;" ::: "memory")
#define CP_WAIT1()  asm volatile("cp.async.wait_group 1;" ::: "memory")
#define CP_WAIT0()  asm volatile("cp.async.wait_group 0;" ::: "memory")

#define LDSM4(R, addr) \
    asm volatile("ldmatrix.sync.aligned.m8n8.x4.shared.b16 {%0,%1,%2,%3}, [%4];" \
        : "=r"((R)[0]), "=r"((R)[1]), "=r"((R)[2]), "=r"((R)[3]) : "r"(addr))

__device__ __forceinline__ void mma16816(float* c, const uint32_t* a,
                                         const uint32_t* b) {
    asm volatile(
        "mma.sync.aligned.m16n8k16.row.col.f32.bf16.bf16.f32 "
        "{%0,%1,%2,%3}, {%4,%5,%6,%7}, {%8,%9}, {%0,%1,%2,%3};"
        : "+f"(c[0]), "+f"(c[1]), "+f"(c[2]), "+f"(c[3])
        : "r"(a[0]), "r"(a[1]), "r"(a[2]), "r"(a[3]), "r"(b[0]), "r"(b[1]));
}

// -------------------- small kernels --------------------
__global__ void k_norm(const float* __restrict__ sig,
                       const float* __restrict__ mean,
                       const float* __restrict__ var) {
    int i = blockIdx.x * blockDim.x + threadIdx.x;
    if (i < V * 3) {
        int c = i % 3;
        g_x[i] = (sig[i] - mean[c]) / sqrtf(var[c]);
    }
}

__device__ __forceinline__ void split_store(float s, __nv_bfloat16* hi,
                                            __nv_bfloat16* lo, size_t i) {
    __nv_bfloat16 h = __float2bfloat16_rn(s);
    hi[i] = h;
    lo[i] = __float2bfloat16_rn(s - __bfloat162float(h));
}

__global__ void k_patch(const int* __restrict__ bc_idx,
                        const float* __restrict__ bc_w,
                        int Cin, int Kpad,
                        __nv_bfloat16* __restrict__ ph,
                        __nv_bfloat16* __restrict__ pl) {
    size_t i = (size_t)blockIdx.x * blockDim.x + threadIdx.x;
    size_t total = (size_t)V * Kpad;
    if (i >= total) return;
    int k = (int)(i % Kpad);
    int v = (int)(i / Kpad);
    float s = 0.f;
    int K = RR * AA * Cin;
    if (k < K) {
        int ra = k / Cin, c = k % Cin;
        const int*   id = bc_idx + ((size_t)v * RR * AA + ra) * 3;
        const float* w  = bc_w   + ((size_t)v * RR * AA + ra) * 3;
        s = g_x[id[0] * Cin + c] * w[0] +
            g_x[id[1] * Cin + c] * w[1] +
            g_x[id[2] * Cin + c] * w[2];
    }
    split_store(s, ph, pl, i);
}

// B[col][k] = W[t, r, (a+n)%A, c]; col = n*TT + t, k = (r*A+a)*Cin + c
__global__ void k_brot(const float* __restrict__ W, int Cin, int Kpad,
                       __nv_bfloat16* __restrict__ bh,
                       __nv_bfloat16* __restrict__ bl) {
    size_t i = (size_t)blockIdx.x * blockDim.x + threadIdx.x;
    size_t total = (size_t)NCONV * Kpad;
    if (i >= total) return;
    int k   = (int)(i % Kpad);
    int col = (int)(i / Kpad);
    float s = 0.f;
    int K = RR * AA * Cin;
    if (k < K) {
        int c = k % Cin, ra = k / Cin;
        int a = ra % AA, r = ra / AA;
        int t = col % TT, n = col / TT;
        int a2 = (a + n) & (AA - 1);
        s = W[((t * RR + r) * AA + a2) * Cin + c];
    }
    split_store(s, bh, bl, i);
}

__global__ void k_xpad() {
    int i = blockIdx.x * blockDim.x + threadIdx.x;
    if (i >= V * KPAD_S) return;
    int k = i % KPAD_S, v = i / KPAD_S;
    float s = (k < TT) ? g_x[v * TT + k] : 0.f;
    split_store(s, g_xhi, g_xlo, i);
}

__global__ void k_dwt(const float* __restrict__ dw) {
    int i = blockIdx.x * blockDim.x + threadIdx.x;
    if (i >= V * KPAD_S) return;
    int k = i % KPAD_S, n = i / KPAD_S;
    float s = (k < TT) ? dw[(size_t)k * V + n] : 0.f;
    split_store(s, g_dhi, g_dlo, i);
}

__global__ void k_amp_bn(const float* __restrict__ gam,
                         const float* __restrict__ bet,
                         const float* __restrict__ mu,
                         const float* __restrict__ var) {
    int warp = (blockIdx.x * blockDim.x + threadIdx.x) / 32;
    int lane = threadIdx.x & 31;
    if (warp >= V) return;
    const float* row = g_conv + (size_t)warp * NCONV;
    float best = -1.f;
    int bestn = 0;
#pragma unroll
    for (int n = 0; n < AA; ++n) {
        float s = 0.f;
        for (int t = lane; t < TT; t += 32) {
            float x = row[n * TT + t];
            s += x * x;
        }
#pragma unroll
        for (int off = 16; off > 0; off >>= 1)
            s += __shfl_xor_sync(0xFFFFFFFFu, s, off);
        if (s > best) { best = s; bestn = n; }
    }
    for (int t = lane; t < TT; t += 32) {
        float x = row[bestn * TT + t];
        g_x[warp * TT + t] = gam[t] * (x - mu[t]) * rsqrtf(var[t] + EPS_BN) + bet[t];
    }
}

// -------------------- HMMA GEMM --------------------
// C[M,N] = Ah@Bh^T + Ah@Bl^T + Al@Bh^T (+bias[col%bias_mod], opt relu)
// A:(M,Kpad) bf16 K-major; B:(N,Kpad) bf16 K-major. 128x128/CTA, BK=32.
#define ROWB   80                    // padded smem row stride (bytes)
#define TILEB  (128 * ROWB)          // 10240
#define STAGEB (4 * TILEB)           // 40960
#define SMEM_BYTES (2 * STAGEB)      // 81920

__device__ __forceinline__ void load_stage(
    uint32_t sm, const __nv_bfloat16* Ah, const __nv_bfloat16* Al,
    const __nv_bfloat16* Bh, const __nv_bfloat16* Bl,
    int row0, int col0, int M, int N, int Kpad, int k0, int tid) {
#pragma unroll
    for (int tI = 0; tI < 4; ++tI) {
        const __nv_bfloat16* src = (tI == 0) ? Ah : (tI == 1) ? Al
                                  : (tI == 2) ? Bh : Bl;
        int rb = (tI < 2) ? row0 : col0;
        int rm = (tI < 2) ? M : N;
#pragma unroll
        for (int it = 0; it < 2; ++it) {
            int idx = tid + it * 256;          // 0..511
            int row = idx >> 2, seg = idx & 3;
            int gr = rb + row;
            if (gr > rm - 1) gr = rm - 1;
            const void* gsrc = src + (size_t)gr * Kpad + k0 + seg * 8;
            uint32_t dst = sm + tI * TILEB + row * ROWB + seg * 16;
            CP_ASYNC16(dst, gsrc);
        }
    }
    CP_COMMIT();
}

__global__ void __launch_bounds__(256)
k_gemm(const __nv_bfloat16* __restrict__ Ah, const __nv_bfloat16* __restrict__ Al,
       const __nv_bfloat16* __restrict__ Bh, const __nv_bfloat16* __restrict__ Bl,
       const float* __restrict__ bias, float* __restrict__ C,
       int M, int N, int Kpad, int bias_mod, int relu) {
    extern __shared__ char dsm[];
    uint32_t sbase = smem_u32(dsm);

    int tid = threadIdx.x, wid = tid >> 5, lane = tid & 31;
    int warp_m = wid & 1, warp_n = wid >> 1;
    int row0 = blockIdx.y * 128, col0 = blockIdx.x * 128;

    float acc[4][4][4];
#pragma unroll
    for (int i = 0; i < 4; ++i)
#pragma unroll
        for (int j = 0; j < 4; ++j)
#pragma unroll
            for (int q = 0; q < 4; ++q) acc[i][j][q] = 0.f;

    int nch = Kpad >> 5;
    load_stage(sbase, Ah, Al, Bh, Bl, row0, col0, M, N, Kpad, 0, tid);
    load_stage(sbase + STAGEB, Ah, Al, Bh, Bl, row0, col0, M, N, Kpad, 32, tid);

    for (int c = 0; c < nch; ++c) {
        if (c + 1 < nch) { CP_WAIT1(); } else { CP_WAIT0(); }
        __syncthreads();
        uint32_t sa = sbase + (c & 1) * STAGEB;

#pragma unroll
        for (int ks = 0; ks < 2; ++ks) {
            uint32_t ah[4][4], al[4][4], bh[2][4], bl[2][4];
            // A frags (hi & lo): rows warp_m*64 + mi*16 + (lane&15)
#pragma unroll
            for (int mi = 0; mi < 4; ++mi) {
                int row = warp_m * 64 + mi * 16 + (lane & 15);
                uint32_t ad = sa + row * ROWB + ks * 32 + ((lane >> 4) << 4);
                LDSM4(ah[mi], ad);
                LDSM4(al[mi], ad + TILEB);
            }
            // B frags: x4 covers two n8-frags; lanes: m=lane>>3:
            //   row = warp_n*32 + bi*16 + ((m>>1)<<3) + (lane&7), koff=(m&1)*16
#pragma unroll
            for (int bi = 0; bi < 2; ++bi) {
                int m = lane >> 3;
                int row = warp_n * 32 + bi * 16 + ((m >> 1) << 3) + (lane & 7);
                uint32_t bd = sa + 2 * TILEB + row * ROWB + ks * 32 + ((m & 1) << 4);
                LDSM4(bh[bi], bd);
                LDSM4(bl[bi], bd + TILEB);
            }
#pragma unroll
            for (int mi = 0; mi < 4; ++mi)
#pragma unroll
                for (int ni = 0; ni < 4; ++ni) {
                    const uint32_t* Bf_h = &bh[ni >> 1][(ni & 1) * 2];
                    const uint32_t* Bf_l = &bl[ni >> 1][(ni & 1) * 2];
                    mma16816(acc[mi][ni], ah[mi], Bf_h);
                    mma16816(acc[mi][ni], ah[mi], Bf_l);
                    mma16816(acc[mi][ni], al[mi], Bf_h);
                }
        }
        __syncthreads();
        if (c + 2 < nch)
            load_stage(sbase + (c & 1) * STAGEB, Ah, Al, Bh, Bl,
                       row0, col0, M, N, Kpad, (c + 2) << 5, tid);
    }

    // epilogue: direct stores, bias + relu
    int rbase = row0 + warp_m * 64;
    int cbase = col0 + warp_n * 32;
#pragma unroll
    for (int mi = 0; mi < 4; ++mi)
#pragma unroll
        for (int ni = 0; ni < 4; ++ni) {
            int r = rbase + mi * 16 + (lane >> 2);
            int cc = cbase + ni * 8 + (lane & 3) * 2;
            if (cc < N) {
                float b0 = bias[cc % bias_mod];
                float b1 = bias[(cc + 1) % bias_mod];
                if (r < M) {
                    float v0 = acc[mi][ni][0] + b0;
                    float v1 = acc[mi][ni][1] + b1;
                    if (relu) { v0 = fmaxf(v0, 0.f); v1 = fmaxf(v1, 0.f); }
                    *(float2*)&C[(size_t)r * N + cc] = make_float2(v0, v1);
                }
                if (r + 8 < M) {
                    float v2 = acc[mi][ni][2] + b0;
                    float v3 = acc[mi][ni][3] + b1;
                    if (relu) { v2 = fmaxf(v2, 0.f); v3 = fmaxf(v3, 0.f); }
                    *(float2*)&C[(size_t)(r + 8) * N + cc] = make_float2(v2, v3);
                }
            }
        }
}

// -------------------- launch --------------------
extern "C" void kernel_launch(void* const* d_in, const int* in_sizes, int n_in,
                              void* d_out, int out_size) {
    const float* signal = (const float*)d_in[0];
    const int*   bc_idx = (const int*)d_in[1];
    const float* bc_w   = (const float*)d_in[2];
    const float* nmean  = (const float*)d_in[3];
    const float* nvar   = (const float*)d_in[4];
    const float* Ws[3]  = {(const float*)d_in[5], (const float*)d_in[7],
                           (const float*)d_in[9]};
    const float* Bls[3] = {(const float*)d_in[6], (const float*)d_in[8],
                           (const float*)d_in[10]};
    const float* bng = (const float*)d_in[11];
    const float* bnb = (const float*)d_in[12];
    const float* bnm = (const float*)d_in[13];
    const float* bnv = (const float*)d_in[14];
    const float* dw  = (const float*)d_in[15];
    const float* db  = (const float*)d_in[16];
    float* out = (float*)d_out;

    cudaFuncSetAttribute(k_gemm, cudaFuncAttributeMaxDynamicSharedMemorySize,
                         SMEM_BYTES);

    __nv_bfloat16 *pPhi, *pPlo, *pBh, *pBl, *pXh, *pXl, *pDh, *pDl;
    float *pConv;
    cudaGetSymbolAddress((void**)&pPhi, g_phi);
    cudaGetSymbolAddress((void**)&pPlo, g_plo);
    cudaGetSymbolAddress((void**)&pBh,  g_bhi);
    cudaGetSymbolAddress((void**)&pBl,  g_blo);
    cudaGetSymbolAddress((void**)&pXh,  g_xhi);
    cudaGetSymbolAddress((void**)&pXl,  g_xlo);
    cudaGetSymbolAddress((void**)&pDh,  g_dhi);
    cudaGetSymbolAddress((void**)&pDl,  g_dlo);
    cudaGetSymbolAddress((void**)&pConv, g_conv);

    k_norm<<<(V * 3 + 255) / 256, 256>>>(signal, nmean, nvar);

    int Cin = 3;
    for (int l = 0; l < 3; ++l) {
        int K = RR * AA * Cin;
        int Kpad = ((K + 31) / 32) * 32;        // 128 / 4032
        size_t totP = (size_t)V * Kpad;
        size_t totB = (size_t)NCONV * Kpad;
        k_patch<<<(unsigned)((totP + 255) / 256), 256>>>(bc_idx, bc_w, Cin, Kpad,
                                                         pPhi, pPlo);
        k_brot<<<(unsigned)((totB + 255) / 256), 256>>>(Ws[l], Cin, Kpad, pBh, pBl);
        dim3 g((NCONV + 127) / 128, (V + 127) / 128);
        k_gemm<<<g, 256, SMEM_BYTES>>>(pPhi, pPlo, pBh, pBl, Bls[l], pConv,
                                       V, NCONV, Kpad, TT, 1);
        k_amp_bn<<<(V + 7) / 8, 256>>>(bng + l * TT, bnb + l * TT,
                                       bnm + l * TT, bnv + l * TT);
        Cin = TT;
    }

    k_xpad<<<(V * KPAD_S + 255) / 256, 256>>>();
    k_dwt<<<(V * KPAD_S + 255) / 256, 256>>>(dw);
    dim3 g2((V + 127) / 128, (V + 127) / 128);
    k_gemm<<<g2, 256, SMEM_BYTES>>>(pXh, pXl, pDh, pDl, db, out,
                                    V, V, KPAD_S, V, 0);
}

// round 4
// speedup vs baseline: 3.4573x; 1.1820x over previous
#include <cuda_runtime.h>
#include <cuda_bf16.h>
#include <cstdint>

// ---------------------------------------------------------------------------
// IMCNN forward. HMMA m16n8k16 bf16 (bf16x3 split, fp32 accum).
// R4: compile-time div/mod in prep kernels (was ~1.3ms of ALU div emulation),
//     __launch_bounds__(256,2) on GEMM for 2 CTA/SM occupancy.
// ---------------------------------------------------------------------------

#define V      6890
#define RR     5
#define AA     8
#define TT     100
#define NCONV  800
#define KPAD_BIG 4032
#define KPAD_S   128
#define EPS_BN 1e-3f

__device__ float g_x[V * TT];
__device__ float g_conv[V * NCONV];
__device__ __align__(16) __nv_bfloat16 g_phi[(size_t)V * KPAD_BIG];
__device__ __align__(16) __nv_bfloat16 g_plo[(size_t)V * KPAD_BIG];
__device__ __align__(16) __nv_bfloat16 g_bhi[(size_t)NCONV * KPAD_BIG];
__device__ __align__(16) __nv_bfloat16 g_blo[(size_t)NCONV * KPAD_BIG];
__device__ __align__(16) __nv_bfloat16 g_xhi[V * KPAD_S];
__device__ __align__(16) __nv_bfloat16 g_xlo[V * KPAD_S];
__device__ __align__(16) __nv_bfloat16 g_dhi[(size_t)V * KPAD_S];
__device__ __align__(16) __nv_bfloat16 g_dlo[(size_t)V * KPAD_S];

// -------------------- PTX helpers --------------------
__device__ __forceinline__ uint32_t smem_u32(const void* p) {
    uint32_t a;
    asm("{ .reg .u64 t; cvta.to.shared.u64 t, %1; cvt.u32.u64 %0, t; }"
        : "=r"(a) : "l"(p));
    return a;
}
#define CP_ASYNC16(dst, src) \
    asm volatile("cp.async.cg.shared.global [%0], [%1], 16;" \
                 :: "r"(dst), "l"(src))
#define CP_COMMIT() asm volatile("cp.async.commit_group;" ::: "memory")
#define CP_WAIT1()  asm volatile("cp.async.wait_group 1;" ::: "memory")
#define CP_WAIT0()  asm volatile("cp.async.wait_group 0;" ::: "memory")

#define LDSM4(R, addr) \
    asm volatile("ldmatrix.sync.aligned.m8n8.x4.shared.b16 {%0,%1,%2,%3}, [%4];" \
        : "=r"((R)[0]), "=r"((R)[1]), "=r"((R)[2]), "=r"((R)[3]) : "r"(addr))

__device__ __forceinline__ void mma16816(float* c, const uint32_t* a,
                                         const uint32_t* b) {
    asm volatile(
        "mma.sync.aligned.m16n8k16.row.col.f32.bf16.bf16.f32 "
        "{%0,%1,%2,%3}, {%4,%5,%6,%7}, {%8,%9}, {%0,%1,%2,%3};"
        : "+f"(c[0]), "+f"(c[1]), "+f"(c[2]), "+f"(c[3])
        : "r"(a[0]), "r"(a[1]), "r"(a[2]), "r"(a[3]), "r"(b[0]), "r"(b[1]));
}

// -------------------- small kernels --------------------
__global__ void k_norm(const float* __restrict__ sig,
                       const float* __restrict__ mean,
                       const float* __restrict__ var) {
    int i = blockIdx.x * blockDim.x + threadIdx.x;
    if (i < V * 3) {
        int c = i % 3;
        g_x[i] = (sig[i] - mean[c]) / sqrtf(var[c]);
    }
}

__device__ __forceinline__ void split_store(float s, __nv_bfloat16* hi,
                                            __nv_bfloat16* lo, size_t i) {
    __nv_bfloat16 h = __float2bfloat16_rn(s);
    hi[i] = h;
    lo[i] = __float2bfloat16_rn(s - __bfloat162float(h));
}

// all div/mod by template constants -> mul-shift
template <int CIN, int KPAD>
__global__ void k_patch(const int* __restrict__ bc_idx,
                        const float* __restrict__ bc_w,
                        __nv_bfloat16* __restrict__ ph,
                        __nv_bfloat16* __restrict__ pl) {
    size_t i = (size_t)blockIdx.x * blockDim.x + threadIdx.x;
    if (i >= (size_t)V * KPAD) return;
    int k = (int)(i % KPAD);
    int v = (int)(i / KPAD);
    float s = 0.f;
    constexpr int K = RR * AA * CIN;
    if (k < K) {
        int ra = k / CIN, c = k % CIN;
        const int*   id = bc_idx + ((size_t)v * RR * AA + ra) * 3;
        const float* w  = bc_w   + ((size_t)v * RR * AA + ra) * 3;
        s = g_x[id[0] * CIN + c] * w[0] +
            g_x[id[1] * CIN + c] * w[1] +
            g_x[id[2] * CIN + c] * w[2];
    }
    split_store(s, ph, pl, i);
}

// B[col][k] = W[t, r, (a+n)%A, c]; col = n*TT + t, k = (r*A+a)*CIN + c
template <int CIN, int KPAD>
__global__ void k_brot(const float* __restrict__ W,
                       __nv_bfloat16* __restrict__ bh,
                       __nv_bfloat16* __restrict__ bl) {
    size_t i = (size_t)blockIdx.x * blockDim.x + threadIdx.x;
    if (i >= (size_t)NCONV * KPAD) return;
    int k   = (int)(i % KPAD);
    int col = (int)(i / KPAD);
    float s = 0.f;
    constexpr int K = RR * AA * CIN;
    if (k < K) {
        int c = k % CIN, ra = k / CIN;
        int a = ra % AA, r = ra / AA;
        int t = col % TT, n = col / TT;
        int a2 = (a + n) & (AA - 1);
        s = W[((t * RR + r) * AA + a2) * CIN + c];
    }
    split_store(s, bh, bl, i);
}

__global__ void k_xpad() {
    int i = blockIdx.x * blockDim.x + threadIdx.x;
    if (i >= V * KPAD_S) return;
    int k = i & (KPAD_S - 1), v = i >> 7;
    float s = (k < TT) ? g_x[v * TT + k] : 0.f;
    split_store(s, g_xhi, g_xlo, i);
}

__global__ void k_dwt(const float* __restrict__ dw) {
    int i = blockIdx.x * blockDim.x + threadIdx.x;
    if (i >= V * KPAD_S) return;
    int k = i & (KPAD_S - 1), n = i >> 7;
    float s = (k < TT) ? dw[(size_t)k * V + n] : 0.f;
    split_store(s, g_dhi, g_dlo, i);
}

__global__ void k_amp_bn(const float* __restrict__ gam,
                         const float* __restrict__ bet,
                         const float* __restrict__ mu,
                         const float* __restrict__ var) {
    int warp = (blockIdx.x * blockDim.x + threadIdx.x) / 32;
    int lane = threadIdx.x & 31;
    if (warp >= V) return;
    const float* row = g_conv + (size_t)warp * NCONV;
    float best = -1.f;
    int bestn = 0;
#pragma unroll
    for (int n = 0; n < AA; ++n) {
        float s = 0.f;
        for (int t = lane; t < TT; t += 32) {
            float x = row[n * TT + t];
            s += x * x;
        }
#pragma unroll
        for (int off = 16; off > 0; off >>= 1)
            s += __shfl_xor_sync(0xFFFFFFFFu, s, off);
        if (s > best) { best = s; bestn = n; }
    }
    for (int t = lane; t < TT; t += 32) {
        float x = row[bestn * TT + t];
        g_x[warp * TT + t] = gam[t] * (x - mu[t]) * rsqrtf(var[t] + EPS_BN) + bet[t];
    }
}

// -------------------- HMMA GEMM --------------------
#define ROWB   80
#define TILEB  (128 * ROWB)
#define STAGEB (4 * TILEB)
#define SMEM_BYTES (2 * STAGEB)      // 81920

__device__ __forceinline__ void load_stage(
    uint32_t sm, const __nv_bfloat16* Ah, const __nv_bfloat16* Al,
    const __nv_bfloat16* Bh, const __nv_bfloat16* Bl,
    int row0, int col0, int M, int N, int Kpad, int k0, int tid) {
#pragma unroll
    for (int tI = 0; tI < 4; ++tI) {
        const __nv_bfloat16* src = (tI == 0) ? Ah : (tI == 1) ? Al
                                  : (tI == 2) ? Bh : Bl;
        int rb = (tI < 2) ? row0 : col0;
        int rm = (tI < 2) ? M : N;
#pragma unroll
        for (int it = 0; it < 2; ++it) {
            int idx = tid + it * 256;
            int row = idx >> 2, seg = idx & 3;
            int gr = rb + row;
            if (gr > rm - 1) gr = rm - 1;
            const void* gsrc = src + (size_t)gr * Kpad + k0 + seg * 8;
            uint32_t dst = sm + tI * TILEB + row * ROWB + seg * 16;
            CP_ASYNC16(dst, gsrc);
        }
    }
    CP_COMMIT();
}

__global__ void __launch_bounds__(256, 2)
k_gemm(const __nv_bfloat16* __restrict__ Ah, const __nv_bfloat16* __restrict__ Al,
       const __nv_bfloat16* __restrict__ Bh, const __nv_bfloat16* __restrict__ Bl,
       const float* __restrict__ bias, float* __restrict__ C,
       int M, int N, int Kpad, int bias_mod, int relu) {
    extern __shared__ char dsm[];
    uint32_t sbase = smem_u32(dsm);

    int tid = threadIdx.x, wid = tid >> 5, lane = tid & 31;
    int warp_m = wid & 1, warp_n = wid >> 1;
    int row0 = blockIdx.y * 128, col0 = blockIdx.x * 128;

    float acc[4][4][4];
#pragma unroll
    for (int i = 0; i < 4; ++i)
#pragma unroll
        for (int j = 0; j < 4; ++j)
#pragma unroll
            for (int q = 0; q < 4; ++q) acc[i][j][q] = 0.f;

    int nch = Kpad >> 5;
    load_stage(sbase, Ah, Al, Bh, Bl, row0, col0, M, N, Kpad, 0, tid);
    load_stage(sbase + STAGEB, Ah, Al, Bh, Bl, row0, col0, M, N, Kpad, 32, tid);

    for (int c = 0; c < nch; ++c) {
        if (c + 1 < nch) { CP_WAIT1(); } else { CP_WAIT0(); }
        __syncthreads();
        uint32_t sa = sbase + (c & 1) * STAGEB;

#pragma unroll
        for (int ks = 0; ks < 2; ++ks) {
            uint32_t ah[4][4], al[4][4], bh[2][4], bl[2][4];
#pragma unroll
            for (int mi = 0; mi < 4; ++mi) {
                int row = warp_m * 64 + mi * 16 + (lane & 15);
                uint32_t ad = sa + row * ROWB + ks * 32 + ((lane >> 4) << 4);
                LDSM4(ah[mi], ad);
                LDSM4(al[mi], ad + TILEB);
            }
#pragma unroll
            for (int bi = 0; bi < 2; ++bi) {
                int m = lane >> 3;
                int row = warp_n * 32 + bi * 16 + ((m >> 1) << 3) + (lane & 7);
                uint32_t bd = sa + 2 * TILEB + row * ROWB + ks * 32 + ((m & 1) << 4);
                LDSM4(bh[bi], bd);
                LDSM4(bl[bi], bd + TILEB);
            }
#pragma unroll
            for (int mi = 0; mi < 4; ++mi)
#pragma unroll
                for (int ni = 0; ni < 4; ++ni) {
                    const uint32_t* Bf_h = &bh[ni >> 1][(ni & 1) * 2];
                    const uint32_t* Bf_l = &bl[ni >> 1][(ni & 1) * 2];
                    mma16816(acc[mi][ni], ah[mi], Bf_h);
                    mma16816(acc[mi][ni], ah[mi], Bf_l);
                    mma16816(acc[mi][ni], al[mi], Bf_h);
                }
        }
        __syncthreads();
        if (c + 2 < nch)
            load_stage(sbase + (c & 1) * STAGEB, Ah, Al, Bh, Bl,
                       row0, col0, M, N, Kpad, (c + 2) << 5, tid);
    }

    int rbase = row0 + warp_m * 64;
    int cbase = col0 + warp_n * 32;
#pragma unroll
    for (int mi = 0; mi < 4; ++mi)
#pragma unroll
        for (int ni = 0; ni < 4; ++ni) {
            int r = rbase + mi * 16 + (lane >> 2);
            int cc = cbase + ni * 8 + (lane & 3) * 2;
            if (cc < N) {
                float b0 = bias[cc % bias_mod];
                float b1 = bias[(cc + 1) % bias_mod];
                if (r < M) {
                    float v0 = acc[mi][ni][0] + b0;
                    float v1 = acc[mi][ni][1] + b1;
                    if (relu) { v0 = fmaxf(v0, 0.f); v1 = fmaxf(v1, 0.f); }
                    *(float2*)&C[(size_t)r * N + cc] = make_float2(v0, v1);
                }
                if (r + 8 < M) {
                    float v2 = acc[mi][ni][2] + b0;
                    float v3 = acc[mi][ni][3] + b1;
                    if (relu) { v2 = fmaxf(v2, 0.f); v3 = fmaxf(v3, 0.f); }
                    *(float2*)&C[(size_t)(r + 8) * N + cc] = make_float2(v2, v3);
                }
            }
        }
}

// -------------------- launch --------------------
extern "C" void kernel_launch(void* const* d_in, const int* in_sizes, int n_in,
                              void* d_out, int out_size) {
    const float* signal = (const float*)d_in[0];
    const int*   bc_idx = (const int*)d_in[1];
    const float* bc_w   = (const float*)d_in[2];
    const float* nmean  = (const float*)d_in[3];
    const float* nvar   = (const float*)d_in[4];
    const float* Ws[3]  = {(const float*)d_in[5], (const float*)d_in[7],
                           (const float*)d_in[9]};
    const float* Bls[3] = {(const float*)d_in[6], (const float*)d_in[8],
                           (const float*)d_in[10]};
    const float* bng = (const float*)d_in[11];
    const float* bnb = (const float*)d_in[12];
    const float* bnm = (const float*)d_in[13];
    const float* bnv = (const float*)d_in[14];
    const float* dw  = (const float*)d_in[15];
    const float* db  = (const float*)d_in[16];
    float* out = (float*)d_out;

    cudaFuncSetAttribute(k_gemm, cudaFuncAttributeMaxDynamicSharedMemorySize,
                         SMEM_BYTES);

    __nv_bfloat16 *pPhi, *pPlo, *pBh, *pBl, *pXh, *pXl, *pDh, *pDl;
    float *pConv;
    cudaGetSymbolAddress((void**)&pPhi, g_phi);
    cudaGetSymbolAddress((void**)&pPlo, g_plo);
    cudaGetSymbolAddress((void**)&pBh,  g_bhi);
    cudaGetSymbolAddress((void**)&pBl,  g_blo);
    cudaGetSymbolAddress((void**)&pXh,  g_xhi);
    cudaGetSymbolAddress((void**)&pXl,  g_xlo);
    cudaGetSymbolAddress((void**)&pDh,  g_dhi);
    cudaGetSymbolAddress((void**)&pDl,  g_dlo);
    cudaGetSymbolAddress((void**)&pConv, g_conv);

    k_norm<<<(V * 3 + 255) / 256, 256>>>(signal, nmean, nvar);

    for (int l = 0; l < 3; ++l) {
        int Kpad = (l == 0) ? 128 : KPAD_BIG;
        size_t totP = (size_t)V * Kpad;
        size_t totB = (size_t)NCONV * Kpad;
        if (l == 0) {
            k_patch<3, 128><<<(unsigned)((totP + 255) / 256), 256>>>(
                bc_idx, bc_w, pPhi, pPlo);
            k_brot<3, 128><<<(unsigned)((totB + 255) / 256), 256>>>(
                Ws[l], pBh, pBl);
        } else {
            k_patch<TT, KPAD_BIG><<<(unsigned)((totP + 255) / 256), 256>>>(
                bc_idx, bc_w, pPhi, pPlo);
            k_brot<TT, KPAD_BIG><<<(unsigned)((totB + 255) / 256), 256>>>(
                Ws[l], pBh, pBl);
        }
        dim3 g((NCONV + 127) / 128, (V + 127) / 128);
        k_gemm<<<g, 256, SMEM_BYTES>>>(pPhi, pPlo, pBh, pBl, Bls[l], pConv,
                                       V, NCONV, Kpad, TT, 1);
        k_amp_bn<<<(V + 7) / 8, 256>>>(bng + l * TT, bnb + l * TT,
                                       bnm + l * TT, bnv + l * TT);
    }

    k_xpad<<<(V * KPAD_S + 255) / 256, 256>>>();
    k_dwt<<<(V * KPAD_S + 255) / 256, 256>>>(dw);
    dim3 g2((V + 127) / 128, (V + 127) / 128);
    k_gemm<<<g2, 256, SMEM_BYTES>>>(pXh, pXl, pDh, pDl, db, out,
                                    V, V, KPAD_S, V, 0);
}

// round 5
// speedup vs baseline: 4.1545x; 1.2017x over previous
#include <cuda_runtime.h>
#include <cuda_bf16.h>
#include <cstdint>

// ---------------------------------------------------------------------------
// IMCNN forward. HMMA m16n8k16 bf16, bf16x3 split (hi/lo interleaved in k),
// fp32 accum. R5: 3-stage cp.async pipeline w/ single barrier per chunk,
// SW128-swizzled smem, k-interleaved hi/lo buffers, vectorized prep.
// ---------------------------------------------------------------------------

#define V      6890
#define RR     5
#define AA     8
#define TT     100
#define NCONV  800
#define KPAD_BIG 4032
#define KPAD_S   128
#define EPS_BN 1e-3f

// interleaved buffers: row stride = 2*Kpad elements; layout per 16-k block:
// [hi k..k+15 (32B)][lo k..k+15 (32B)]
__device__ float g_x[V * TT];
__device__ float g_conv[V * NCONV];
__device__ __align__(16) __nv_bfloat16 g_pa[(size_t)V * 2 * KPAD_BIG];
__device__ __align__(16) __nv_bfloat16 g_bb[(size_t)NCONV * 2 * KPAD_BIG];
__device__ __align__(16) __nv_bfloat16 g_xx[(size_t)V * 2 * KPAD_S];
__device__ __align__(16) __nv_bfloat16 g_dd[(size_t)V * 2 * KPAD_S];

// -------------------- PTX helpers --------------------
__device__ __forceinline__ uint32_t smem_u32(const void* p) {
    uint32_t a;
    asm("{ .reg .u64 t; cvta.to.shared.u64 t, %1; cvt.u32.u64 %0, t; }"
        : "=r"(a) : "l"(p));
    return a;
}
#define CP_ASYNC16(dst, src) \
    asm volatile("cp.async.cg.shared.global [%0], [%1], 16;" \
                 :: "r"(dst), "l"(src))
#define CP_COMMIT() asm volatile("cp.async.commit_group;" ::: "memory")
#define CP_WAIT1()  asm volatile("cp.async.wait_group 1;" ::: "memory")
#define CP_WAIT0()  asm volatile("cp.async.wait_group 0;" ::: "memory")

#define LDSM4(R, addr) \
    asm volatile("ldmatrix.sync.aligned.m8n8.x4.shared.b16 {%0,%1,%2,%3}, [%4];" \
        : "=r"((R)[0]), "=r"((R)[1]), "=r"((R)[2]), "=r"((R)[3]) : "r"(addr))

#define SWZ(o) ((o) ^ (((o) >> 3) & 0x70))

__device__ __forceinline__ void mma16816(float* c, const uint32_t* a,
                                         const uint32_t* b) {
    asm volatile(
        "mma.sync.aligned.m16n8k16.row.col.f32.bf16.bf16.f32 "
        "{%0,%1,%2,%3}, {%4,%5,%6,%7}, {%8,%9}, {%0,%1,%2,%3};"
        : "+f"(c[0]), "+f"(c[1]), "+f"(c[2]), "+f"(c[3])
        : "r"(a[0]), "r"(a[1]), "r"(a[2]), "r"(a[3]), "r"(b[0]), "r"(b[1]));
}

// -------------------- small kernels --------------------
__global__ void k_norm(const float* __restrict__ sig,
                       const float* __restrict__ mean,
                       const float* __restrict__ var) {
    int i = blockIdx.x * blockDim.x + threadIdx.x;
    if (i < V * 3) {
        int c = i % 3;
        g_x[i] = (sig[i] - mean[c]) / sqrtf(var[c]);
    }
}

// split 4 floats -> 8B hi + 8B lo at interleaved position
__device__ __forceinline__ void store4(__nv_bfloat16* buf, size_t rowbase,
                                       int k0, const float* s) {
    int kb = k0 >> 4, pos = k0 & 15;
    __nv_bfloat16 hv[4], lv[4];
#pragma unroll
    for (int e = 0; e < 4; ++e) {
        hv[e] = __float2bfloat16_rn(s[e]);
        lv[e] = __float2bfloat16_rn(s[e] - __bfloat162float(hv[e]));
    }
    size_t base = rowbase + (size_t)(kb * 32 + pos);
    *(uint2*)(buf + base)      = *(const uint2*)hv;
    *(uint2*)(buf + base + 16) = *(const uint2*)lv;
}

template <int CIN, int KPAD>
__global__ void k_patch(const int* __restrict__ bc_idx,
                        const float* __restrict__ bc_w,
                        __nv_bfloat16* __restrict__ pa) {
    constexpr int QK = KPAD / 4;
    constexpr int K = RR * AA * CIN;
    int i = blockIdx.x * blockDim.x + threadIdx.x;
    if (i >= V * QK) return;
    int q = i % QK, v = i / QK;
    int k0 = q * 4;
    float s[4] = {0.f, 0.f, 0.f, 0.f};
    if (k0 < K) {
        if (CIN % 4 == 0) {            // 4-group never straddles ra
            int ra = k0 / CIN, c0 = k0 % CIN;
            const int*   id = bc_idx + ((size_t)v * (RR * AA) + ra) * 3;
            const float* w  = bc_w   + ((size_t)v * (RR * AA) + ra) * 3;
            int i0 = id[0] * CIN, i1 = id[1] * CIN, i2 = id[2] * CIN;
            float w0 = w[0], w1 = w[1], w2 = w[2];
#pragma unroll
            for (int e = 0; e < 4; ++e)
                s[e] = g_x[i0 + c0 + e] * w0 + g_x[i1 + c0 + e] * w1 +
                       g_x[i2 + c0 + e] * w2;
        } else {
#pragma unroll
            for (int e = 0; e < 4; ++e) {
                int k = k0 + e;
                if (k < K) {
                    int ra = k / CIN, c = k % CIN;
                    const int*   id = bc_idx + ((size_t)v * (RR * AA) + ra) * 3;
                    const float* w  = bc_w   + ((size_t)v * (RR * AA) + ra) * 3;
                    s[e] = g_x[id[0] * CIN + c] * w[0] +
                           g_x[id[1] * CIN + c] * w[1] +
                           g_x[id[2] * CIN + c] * w[2];
                }
            }
        }
    }
    store4(pa, (size_t)v * (2 * KPAD), k0, s);
}

template <int CIN, int KPAD>
__global__ void k_brot(const float* __restrict__ W,
                       __nv_bfloat16* __restrict__ bb) {
    constexpr int QK = KPAD / 4;
    constexpr int K = RR * AA * CIN;
    int i = blockIdx.x * blockDim.x + threadIdx.x;
    if (i >= NCONV * QK) return;
    int q = i % QK, col = i / QK;
    int k0 = q * 4;
    int t = col % TT, n = col / TT;
    float s[4] = {0.f, 0.f, 0.f, 0.f};
#pragma unroll
    for (int e = 0; e < 4; ++e) {
        int k = k0 + e;
        if (k < K) {
            int c = k % CIN, ra = k / CIN;
            int a = ra & (AA - 1), r = ra >> 3;
            int a2 = (a + n) & (AA - 1);
            s[e] = W[((t * RR + r) * AA + a2) * CIN + c];
        }
    }
    store4(bb, (size_t)col * (2 * KPAD), k0, s);
}

__global__ void k_xpad() {
    int i = blockIdx.x * blockDim.x + threadIdx.x;
    if (i >= V * 32) return;
    int v = i >> 5, k0 = (i & 31) * 4;
    float s[4];
#pragma unroll
    for (int e = 0; e < 4; ++e)
        s[e] = (k0 + e < TT) ? g_x[v * TT + k0 + e] : 0.f;
    store4(g_xx, (size_t)v * (2 * KPAD_S), k0, s);
}

__global__ void k_dwt(const float* __restrict__ dw) {
    int i = blockIdx.x * blockDim.x + threadIdx.x;
    if (i >= V * 32) return;
    int n = i >> 5, k0 = (i & 31) * 4;
    float s[4];
#pragma unroll
    for (int e = 0; e < 4; ++e)
        s[e] = (k0 + e < TT) ? dw[(size_t)(k0 + e) * V + n] : 0.f;
    store4(g_dd, (size_t)n * (2 * KPAD_S), k0, s);
}

__global__ void k_amp_bn(const float* __restrict__ gam,
                         const float* __restrict__ bet,
                         const float* __restrict__ mu,
                         const float* __restrict__ var) {
    int warp = (blockIdx.x * blockDim.x + threadIdx.x) / 32;
    int lane = threadIdx.x & 31;
    if (warp >= V) return;
    const float* row = g_conv + (size_t)warp * NCONV;
    float best = -1.f;
    int bestn = 0;
#pragma unroll
    for (int n = 0; n < AA; ++n) {
        float s = 0.f;
        for (int t = lane; t < TT; t += 32) {
            float x = row[n * TT + t];
            s += x * x;
        }
#pragma unroll
        for (int off = 16; off > 0; off >>= 1)
            s += __shfl_xor_sync(0xFFFFFFFFu, s, off);
        if (s > best) { best = s; bestn = n; }
    }
    for (int t = lane; t < TT; t += 32) {
        float x = row[bestn * TT + t];
        g_x[warp * TT + t] = gam[t] * (x - mu[t]) * rsqrtf(var[t] + EPS_BN) + bet[t];
    }
}

// -------------------- HMMA GEMM (3-stage pipeline) --------------------
// stage = A tile (128 x 128B) + B tile (128 x 128B) = 32KB; 3 stages.
#define STGB 32768
#define SMEM_BYTES (3 * STGB + 1024)

__device__ __forceinline__ void load_stage(
    uint32_t sm, const __nv_bfloat16* A2, const __nv_bfloat16* B2,
    int row0, int col0, int M, int N, size_t KP2, int chunk, int tid) {
#pragma unroll
    for (int tI = 0; tI < 2; ++tI) {
        const __nv_bfloat16* src = tI ? B2 : A2;
        int rb = tI ? col0 : row0;
        int rm = tI ? N : M;
#pragma unroll
        for (int it = 0; it < 4; ++it) {
            int idx = tid + it * 256;
            int row = idx >> 3, seg = idx & 7;
            int gr = rb + row;
            if (gr > rm - 1) gr = rm - 1;
            const void* g = src + (size_t)gr * KP2 + (size_t)chunk * 64 + seg * 8;
            uint32_t dst = sm + tI * 16384 + SWZ((uint32_t)(row * 128 + seg * 16));
            CP_ASYNC16(dst, g);
        }
    }
    CP_COMMIT();
}

__global__ void __launch_bounds__(256, 2)
k_gemm(const __nv_bfloat16* __restrict__ A2, const __nv_bfloat16* __restrict__ B2,
       const float* __restrict__ bias, float* __restrict__ C,
       int M, int N, int Kpad, int bias_mod, int relu) {
    extern __shared__ char dsm[];
    uint32_t raw = smem_u32(dsm);
    uint32_t sbase = (raw + 1023u) & ~1023u;

    int tid = threadIdx.x, wid = tid >> 5, lane = tid & 31;
    int warp_m = wid & 1, warp_n = wid >> 1;
    int row0 = blockIdx.y * 128, col0 = blockIdx.x * 128;
    size_t KP2 = 2 * (size_t)Kpad;

    float acc[4][4][4];
#pragma unroll
    for (int i = 0; i < 4; ++i)
#pragma unroll
        for (int j = 0; j < 4; ++j)
#pragma unroll
            for (int q = 0; q < 4; ++q) acc[i][j][q] = 0.f;

    int nch = Kpad >> 5;    // 32 real k per chunk (one 128B interleaved row)
    load_stage(sbase,        A2, B2, row0, col0, M, N, KP2, 0, tid);
    load_stage(sbase + STGB, A2, B2, row0, col0, M, N, KP2, 1, tid);

    int slot = 0;
    for (int c = 0; c < nch; ++c) {
        if (c + 1 < nch) { CP_WAIT1(); } else { CP_WAIT0(); }
        __syncthreads();
        if (c + 2 < nch) {
            int wslot = slot + 2; if (wslot >= 3) wslot -= 3;
            load_stage(sbase + wslot * STGB, A2, B2, row0, col0, M, N, KP2,
                       c + 2, tid);
        }
        uint32_t sa = sbase + slot * STGB;
        if (++slot == 3) slot = 0;

#pragma unroll
        for (int ks = 0; ks < 2; ++ks) {
            uint32_t ah[4][4], al[4][4], bh[2][4], bl[2][4];
#pragma unroll
            for (int mi = 0; mi < 4; ++mi) {
                int arow = warp_m * 64 + mi * 16 + (lane & 15);
                uint32_t off = (uint32_t)(arow * 128 + ks * 64 + ((lane >> 4) << 4));
                LDSM4(ah[mi], sa + SWZ(off));
                LDSM4(al[mi], sa + SWZ(off + 32));
            }
#pragma unroll
            for (int bi = 0; bi < 2; ++bi) {
                int m = lane >> 3;
                int brow = warp_n * 32 + bi * 16 + ((m >> 1) << 3) + (lane & 7);
                uint32_t off = (uint32_t)(brow * 128 + ks * 64 + ((m & 1) << 4));
                LDSM4(bh[bi], sa + 16384 + SWZ(off));
                LDSM4(bl[bi], sa + 16384 + SWZ(off + 32));
            }
#pragma unroll
            for (int mi = 0; mi < 4; ++mi)
#pragma unroll
                for (int ni = 0; ni < 4; ++ni) {
                    const uint32_t* Bf_h = &bh[ni >> 1][(ni & 1) * 2];
                    const uint32_t* Bf_l = &bl[ni >> 1][(ni & 1) * 2];
                    mma16816(acc[mi][ni], ah[mi], Bf_h);
                    mma16816(acc[mi][ni], ah[mi], Bf_l);
                    mma16816(acc[mi][ni], al[mi], Bf_h);
                }
        }
    }

    int rbase = row0 + warp_m * 64;
    int cbase = col0 + warp_n * 32;
#pragma unroll
    for (int mi = 0; mi < 4; ++mi)
#pragma unroll
        for (int ni = 0; ni < 4; ++ni) {
            int r = rbase + mi * 16 + (lane >> 2);
            int cc = cbase + ni * 8 + (lane & 3) * 2;
            if (cc < N) {
                float b0 = bias[cc % bias_mod];
                float b1 = bias[(cc + 1) % bias_mod];
                if (r < M) {
                    float v0 = acc[mi][ni][0] + b0;
                    float v1 = acc[mi][ni][1] + b1;
                    if (relu) { v0 = fmaxf(v0, 0.f); v1 = fmaxf(v1, 0.f); }
                    *(float2*)&C[(size_t)r * N + cc] = make_float2(v0, v1);
                }
                if (r + 8 < M) {
                    float v2 = acc[mi][ni][2] + b0;
                    float v3 = acc[mi][ni][3] + b1;
                    if (relu) { v2 = fmaxf(v2, 0.f); v3 = fmaxf(v3, 0.f); }
                    *(float2*)&C[(size_t)(r + 8) * N + cc] = make_float2(v2, v3);
                }
            }
        }
}

// -------------------- launch --------------------
extern "C" void kernel_launch(void* const* d_in, const int* in_sizes, int n_in,
                              void* d_out, int out_size) {
    const float* signal = (const float*)d_in[0];
    const int*   bc_idx = (const int*)d_in[1];
    const float* bc_w   = (const float*)d_in[2];
    const float* nmean  = (const float*)d_in[3];
    const float* nvar   = (const float*)d_in[4];
    const float* Ws[3]  = {(const float*)d_in[5], (const float*)d_in[7],
                           (const float*)d_in[9]};
    const float* Bls[3] = {(const float*)d_in[6], (const float*)d_in[8],
                           (const float*)d_in[10]};
    const float* bng = (const float*)d_in[11];
    const float* bnb = (const float*)d_in[12];
    const float* bnm = (const float*)d_in[13];
    const float* bnv = (const float*)d_in[14];
    const float* dw  = (const float*)d_in[15];
    const float* db  = (const float*)d_in[16];
    float* out = (float*)d_out;

    cudaFuncSetAttribute(k_gemm, cudaFuncAttributeMaxDynamicSharedMemorySize,
                         SMEM_BYTES);

    __nv_bfloat16 *pPA, *pBB, *pXX, *pDD;
    float *pConv;
    cudaGetSymbolAddress((void**)&pPA, g_pa);
    cudaGetSymbolAddress((void**)&pBB, g_bb);
    cudaGetSymbolAddress((void**)&pXX, g_xx);
    cudaGetSymbolAddress((void**)&pDD, g_dd);
    cudaGetSymbolAddress((void**)&pConv, g_conv);

    k_norm<<<(V * 3 + 255) / 256, 256>>>(signal, nmean, nvar);

    for (int l = 0; l < 3; ++l) {
        int Kpad = (l == 0) ? KPAD_S : KPAD_BIG;
        int nP = V * (Kpad / 4);
        int nB = NCONV * (Kpad / 4);
        if (l == 0) {
            k_patch<3, KPAD_S><<<(nP + 255) / 256, 256>>>(bc_idx, bc_w, pPA);
            k_brot<3, KPAD_S><<<(nB + 255) / 256, 256>>>(Ws[l], pBB);
        } else {
            k_patch<TT, KPAD_BIG><<<(nP + 255) / 256, 256>>>(bc_idx, bc_w, pPA);
            k_brot<TT, KPAD_BIG><<<(nB + 255) / 256, 256>>>(Ws[l], pBB);
        }
        dim3 g((NCONV + 127) / 128, (V + 127) / 128);
        k_gemm<<<g, 256, SMEM_BYTES>>>(pPA, pBB, Bls[l], pConv,
                                       V, NCONV, Kpad, TT, 1);
        k_amp_bn<<<(V + 7) / 8, 256>>>(bng + l * TT, bnb + l * TT,
                                       bnm + l * TT, bnv + l * TT);
    }

    k_xpad<<<(V * 32 + 255) / 256, 256>>>();
    k_dwt<<<(V * 32 + 255) / 256, 256>>>(dw);
    dim3 g2((V + 127) / 128, (V + 127) / 128);
    k_gemm<<<g2, 256, SMEM_BYTES>>>(pXX, pDD, db, out, V, V, KPAD_S, V, 0);
}

// round 6
// speedup vs baseline: 4.7513x; 1.1436x over previous
#include <cuda_runtime.h>
#include <cuda_bf16.h>
#include <cstdint>

// ---------------------------------------------------------------------------
// IMCNN forward. HMMA m16n8k16 bf16, bf16x3 split, fp32 accum.
// R6: split-K x2 on big conv GEMMs (wave quantization 2T -> 1.5T),
//     pass-major MMA ordering (acc reuse distance 1 -> 16),
//     bias+relu+partial-reduce fused into amp_bn.
// ---------------------------------------------------------------------------

#define V      6890
#define RR     5
#define AA     8
#define TT     100
#define NCONV  800
#define KPAD_BIG 4032
#define KPAD_S   128
#define EPS_BN 1e-3f

__device__ float g_x[V * TT];
__device__ float g_conv[2 * V * NCONV];        // two split-K partials
__device__ __align__(16) __nv_bfloat16 g_pa[(size_t)V * 2 * KPAD_BIG];
__device__ __align__(16) __nv_bfloat16 g_bb[(size_t)NCONV * 2 * KPAD_BIG];
__device__ __align__(16) __nv_bfloat16 g_xx[(size_t)V * 2 * KPAD_S];
__device__ __align__(16) __nv_bfloat16 g_dd[(size_t)V * 2 * KPAD_S];

// -------------------- PTX helpers --------------------
__device__ __forceinline__ uint32_t smem_u32(const void* p) {
    uint32_t a;
    asm("{ .reg .u64 t; cvta.to.shared.u64 t, %1; cvt.u32.u64 %0, t; }"
        : "=r"(a) : "l"(p));
    return a;
}
#define CP_ASYNC16(dst, src) \
    asm volatile("cp.async.cg.shared.global [%0], [%1], 16;" \
                 :: "r"(dst), "l"(src))
#define CP_COMMIT() asm volatile("cp.async.commit_group;" ::: "memory")
#define CP_WAIT1()  asm volatile("cp.async.wait_group 1;" ::: "memory")
#define CP_WAIT0()  asm volatile("cp.async.wait_group 0;" ::: "memory")

#define LDSM4(R, addr) \
    asm volatile("ldmatrix.sync.aligned.m8n8.x4.shared.b16 {%0,%1,%2,%3}, [%4];" \
        : "=r"((R)[0]), "=r"((R)[1]), "=r"((R)[2]), "=r"((R)[3]) : "r"(addr))

#define SWZ(o) ((o) ^ (((o) >> 3) & 0x70))

__device__ __forceinline__ void mma16816(float* c, const uint32_t* a,
                                         const uint32_t* b) {
    asm volatile(
        "mma.sync.aligned.m16n8k16.row.col.f32.bf16.bf16.f32 "
        "{%0,%1,%2,%3}, {%4,%5,%6,%7}, {%8,%9}, {%0,%1,%2,%3};"
        : "+f"(c[0]), "+f"(c[1]), "+f"(c[2]), "+f"(c[3])
        : "r"(a[0]), "r"(a[1]), "r"(a[2]), "r"(a[3]), "r"(b[0]), "r"(b[1]));
}

// -------------------- small kernels --------------------
__global__ void k_norm(const float* __restrict__ sig,
                       const float* __restrict__ mean,
                       const float* __restrict__ var) {
    int i = blockIdx.x * blockDim.x + threadIdx.x;
    if (i < V * 3) {
        int c = i % 3;
        g_x[i] = (sig[i] - mean[c]) / sqrtf(var[c]);
    }
}

__device__ __forceinline__ void store4(__nv_bfloat16* buf, size_t rowbase,
                                       int k0, const float* s) {
    int kb = k0 >> 4, pos = k0 & 15;
    __nv_bfloat16 hv[4], lv[4];
#pragma unroll
    for (int e = 0; e < 4; ++e) {
        hv[e] = __float2bfloat16_rn(s[e]);
        lv[e] = __float2bfloat16_rn(s[e] - __bfloat162float(hv[e]));
    }
    size_t base = rowbase + (size_t)(kb * 32 + pos);
    *(uint2*)(buf + base)      = *(const uint2*)hv;
    *(uint2*)(buf + base + 16) = *(const uint2*)lv;
}

template <int CIN, int KPAD>
__global__ void k_patch(const int* __restrict__ bc_idx,
                        const float* __restrict__ bc_w,
                        __nv_bfloat16* __restrict__ pa) {
    constexpr int QK = KPAD / 4;
    constexpr int K = RR * AA * CIN;
    int i = blockIdx.x * blockDim.x + threadIdx.x;
    if (i >= V * QK) return;
    int q = i % QK, v = i / QK;
    int k0 = q * 4;
    float s[4] = {0.f, 0.f, 0.f, 0.f};
    if (k0 < K) {
        if (CIN % 4 == 0) {
            int ra = k0 / CIN, c0 = k0 % CIN;
            const int*   id = bc_idx + ((size_t)v * (RR * AA) + ra) * 3;
            const float* w  = bc_w   + ((size_t)v * (RR * AA) + ra) * 3;
            int i0 = id[0] * CIN, i1 = id[1] * CIN, i2 = id[2] * CIN;
            float w0 = w[0], w1 = w[1], w2 = w[2];
#pragma unroll
            for (int e = 0; e < 4; ++e)
                s[e] = g_x[i0 + c0 + e] * w0 + g_x[i1 + c0 + e] * w1 +
                       g_x[i2 + c0 + e] * w2;
        } else {
#pragma unroll
            for (int e = 0; e < 4; ++e) {
                int k = k0 + e;
                if (k < K) {
                    int ra = k / CIN, c = k % CIN;
                    const int*   id = bc_idx + ((size_t)v * (RR * AA) + ra) * 3;
                    const float* w  = bc_w   + ((size_t)v * (RR * AA) + ra) * 3;
                    s[e] = g_x[id[0] * CIN + c] * w[0] +
                           g_x[id[1] * CIN + c] * w[1] +
                           g_x[id[2] * CIN + c] * w[2];
                }
            }
        }
    }
    store4(pa, (size_t)v * (2 * KPAD), k0, s);
}

template <int CIN, int KPAD>
__global__ void k_brot(const float* __restrict__ W,
                       __nv_bfloat16* __restrict__ bb) {
    constexpr int QK = KPAD / 4;
    constexpr int K = RR * AA * CIN;
    int i = blockIdx.x * blockDim.x + threadIdx.x;
    if (i >= NCONV * QK) return;
    int q = i % QK, col = i / QK;
    int k0 = q * 4;
    int t = col % TT, n = col / TT;
    float s[4] = {0.f, 0.f, 0.f, 0.f};
#pragma unroll
    for (int e = 0; e < 4; ++e) {
        int k = k0 + e;
        if (k < K) {
            int c = k % CIN, ra = k / CIN;
            int a = ra & (AA - 1), r = ra >> 3;
            int a2 = (a + n) & (AA - 1);
            s[e] = W[((t * RR + r) * AA + a2) * CIN + c];
        }
    }
    store4(bb, (size_t)col * (2 * KPAD), k0, s);
}

__global__ void k_xpad() {
    int i = blockIdx.x * blockDim.x + threadIdx.x;
    if (i >= V * 32) return;
    int v = i >> 5, k0 = (i & 31) * 4;
    float s[4];
#pragma unroll
    for (int e = 0; e < 4; ++e)
        s[e] = (k0 + e < TT) ? g_x[v * TT + k0 + e] : 0.f;
    store4(g_xx, (size_t)v * (2 * KPAD_S), k0, s);
}

__global__ void k_dwt(const float* __restrict__ dw) {
    int i = blockIdx.x * blockDim.x + threadIdx.x;
    if (i >= V * 32) return;
    int n = i >> 5, k0 = (i & 31) * 4;
    float s[4];
#pragma unroll
    for (int e = 0; e < 4; ++e)
        s[e] = (k0 + e < TT) ? dw[(size_t)(k0 + e) * V + n] : 0.f;
    store4(g_dd, (size_t)n * (2 * KPAD_S), k0, s);
}

// AMP: reduce NP split-K partials + bias, relu, first-max rotation, BN.
template <int NP>
__global__ void k_amp_bn(const float* __restrict__ bias,
                         const float* __restrict__ gam,
                         const float* __restrict__ bet,
                         const float* __restrict__ mu,
                         const float* __restrict__ var) {
    int warp = (blockIdx.x * blockDim.x + threadIdx.x) / 32;
    int lane = threadIdx.x & 31;
    if (warp >= V) return;
    const float* r0 = g_conv + (size_t)warp * NCONV;
    const float* r1 = r0 + (size_t)V * NCONV;
    float best = -1.f;
    int bestn = 0;
#pragma unroll
    for (int n = 0; n < AA; ++n) {
        float s = 0.f;
        for (int t = lane; t < TT; t += 32) {
            float x = r0[n * TT + t];
            if (NP == 2) x += r1[n * TT + t];
            x = fmaxf(x + bias[t], 0.f);
            s += x * x;
        }
#pragma unroll
        for (int off = 16; off > 0; off >>= 1)
            s += __shfl_xor_sync(0xFFFFFFFFu, s, off);
        if (s > best) { best = s; bestn = n; }
    }
    for (int t = lane; t < TT; t += 32) {
        float x = r0[bestn * TT + t];
        if (NP == 2) x += r1[bestn * TT + t];
        x = fmaxf(x + bias[t], 0.f);
        g_x[warp * TT + t] = gam[t] * (x - mu[t]) * rsqrtf(var[t] + EPS_BN) + bet[t];
    }
}

// -------------------- HMMA GEMM (3-stage, split-K via blockIdx.z) ----------
#define STGB 32768
#define SMEM_BYTES (3 * STGB + 1024)

__device__ __forceinline__ void load_stage(
    uint32_t sm, const __nv_bfloat16* A2, const __nv_bfloat16* B2,
    int row0, int col0, int M, int N, size_t KP2, int chunk, int tid) {
#pragma unroll
    for (int tI = 0; tI < 2; ++tI) {
        const __nv_bfloat16* src = tI ? B2 : A2;
        int rb = tI ? col0 : row0;
        int rm = tI ? N : M;
#pragma unroll
        for (int it = 0; it < 4; ++it) {
            int idx = tid + it * 256;
            int row = idx >> 3, seg = idx & 7;
            int gr = rb + row;
            if (gr > rm - 1) gr = rm - 1;
            const void* g = src + (size_t)gr * KP2 + (size_t)chunk * 64 + seg * 8;
            uint32_t dst = sm + tI * 16384 + SWZ((uint32_t)(row * 128 + seg * 16));
            CP_ASYNC16(dst, g);
        }
    }
    CP_COMMIT();
}

// mode 0: raw partial to C + part*M*N. mode 1: C += bias[col] (dense head).
__global__ void __launch_bounds__(256, 2)
k_gemm(const __nv_bfloat16* __restrict__ A2, const __nv_bfloat16* __restrict__ B2,
       const float* __restrict__ bias, float* __restrict__ C,
       int M, int N, int Kpad, int mode, int chPer) {
    extern __shared__ char dsm[];
    uint32_t raw = smem_u32(dsm);
    uint32_t sbase = (raw + 1023u) & ~1023u;

    int tid = threadIdx.x, wid = tid >> 5, lane = tid & 31;
    int warp_m = wid & 1, warp_n = wid >> 1;
    int row0 = blockIdx.y * 128, col0 = blockIdx.x * 128;
    int part = blockIdx.z;
    int nchTot = Kpad >> 5;
    int kc0 = part * chPer;
    int kc1 = kc0 + chPer; if (kc1 > nchTot) kc1 = nchTot;
    float* Cp = C + (size_t)part * M * N;
    size_t KP2 = 2 * (size_t)Kpad;

    float acc[4][4][4];
#pragma unroll
    for (int i = 0; i < 4; ++i)
#pragma unroll
        for (int j = 0; j < 4; ++j)
#pragma unroll
            for (int q = 0; q < 4; ++q) acc[i][j][q] = 0.f;

    load_stage(sbase,        A2, B2, row0, col0, M, N, KP2, kc0, tid);
    load_stage(sbase + STGB, A2, B2, row0, col0, M, N, KP2, kc0 + 1, tid);

    int slot = 0;
    for (int c = kc0; c < kc1; ++c) {
        if (c + 1 < kc1) { CP_WAIT1(); } else { CP_WAIT0(); }
        __syncthreads();
        if (c + 2 < kc1) {
            int wslot = slot + 2; if (wslot >= 3) wslot -= 3;
            load_stage(sbase + wslot * STGB, A2, B2, row0, col0, M, N, KP2,
                       c + 2, tid);
        }
        uint32_t sa = sbase + slot * STGB;
        if (++slot == 3) slot = 0;

#pragma unroll
        for (int ks = 0; ks < 2; ++ks) {
            uint32_t ah[4][4], al[4][4], bh[2][4], bl[2][4];
#pragma unroll
            for (int mi = 0; mi < 4; ++mi) {
                int arow = warp_m * 64 + mi * 16 + (lane & 15);
                uint32_t off = (uint32_t)(arow * 128 + ks * 64 + ((lane >> 4) << 4));
                LDSM4(ah[mi], sa + SWZ(off));
                LDSM4(al[mi], sa + SWZ(off + 32));
            }
#pragma unroll
            for (int bi = 0; bi < 2; ++bi) {
                int m = lane >> 3;
                int brow = warp_n * 32 + bi * 16 + ((m >> 1) << 3) + (lane & 7);
                uint32_t off = (uint32_t)(brow * 128 + ks * 64 + ((m & 1) << 4));
                LDSM4(bh[bi], sa + 16384 + SWZ(off));
                LDSM4(bl[bi], sa + 16384 + SWZ(off + 32));
            }
            // pass-major: 16 independent MMAs between accumulator reuses
#pragma unroll
            for (int mi = 0; mi < 4; ++mi)
#pragma unroll
                for (int ni = 0; ni < 4; ++ni)
                    mma16816(acc[mi][ni], ah[mi], &bh[ni >> 1][(ni & 1) * 2]);
#pragma unroll
            for (int mi = 0; mi < 4; ++mi)
#pragma unroll
                for (int ni = 0; ni < 4; ++ni)
                    mma16816(acc[mi][ni], ah[mi], &bl[ni >> 1][(ni & 1) * 2]);
#pragma unroll
            for (int mi = 0; mi < 4; ++mi)
#pragma unroll
                for (int ni = 0; ni < 4; ++ni)
                    mma16816(acc[mi][ni], al[mi], &bh[ni >> 1][(ni & 1) * 2]);
        }
    }

    int rbase = row0 + warp_m * 64;
    int cbase = col0 + warp_n * 32;
#pragma unroll
    for (int mi = 0; mi < 4; ++mi)
#pragma unroll
        for (int ni = 0; ni < 4; ++ni) {
            int r = rbase + mi * 16 + (lane >> 2);
            int cc = cbase + ni * 8 + (lane & 3) * 2;
            if (cc < N) {
                float b0 = mode ? bias[cc] : 0.f;
                float b1 = mode ? bias[cc + 1] : 0.f;
                if (r < M)
                    *(float2*)&Cp[(size_t)r * N + cc] =
                        make_float2(acc[mi][ni][0] + b0, acc[mi][ni][1] + b1);
                if (r + 8 < M)
                    *(float2*)&Cp[(size_t)(r + 8) * N + cc] =
                        make_float2(acc[mi][ni][2] + b0, acc[mi][ni][3] + b1);
            }
        }
}

// -------------------- launch --------------------
extern "C" void kernel_launch(void* const* d_in, const int* in_sizes, int n_in,
                              void* d_out, int out_size) {
    const float* signal = (const float*)d_in[0];
    const int*   bc_idx = (const int*)d_in[1];
    const float* bc_w   = (const float*)d_in[2];
    const float* nmean  = (const float*)d_in[3];
    const float* nvar   = (const float*)d_in[4];
    const float* Ws[3]  = {(const float*)d_in[5], (const float*)d_in[7],
                           (const float*)d_in[9]};
    const float* Bls[3] = {(const float*)d_in[6], (const float*)d_in[8],
                           (const float*)d_in[10]};
    const float* bng = (const float*)d_in[11];
    const float* bnb = (const float*)d_in[12];
    const float* bnm = (const float*)d_in[13];
    const float* bnv = (const float*)d_in[14];
    const float* dw  = (const float*)d_in[15];
    const float* db  = (const float*)d_in[16];
    float* out = (float*)d_out;

    cudaFuncSetAttribute(k_gemm, cudaFuncAttributeMaxDynamicSharedMemorySize,
                         SMEM_BYTES);

    __nv_bfloat16 *pPA, *pBB, *pXX, *pDD;
    float *pConv;
    cudaGetSymbolAddress((void**)&pPA, g_pa);
    cudaGetSymbolAddress((void**)&pBB, g_bb);
    cudaGetSymbolAddress((void**)&pXX, g_xx);
    cudaGetSymbolAddress((void**)&pDD, g_dd);
    cudaGetSymbolAddress((void**)&pConv, g_conv);

    k_norm<<<(V * 3 + 255) / 256, 256>>>(signal, nmean, nvar);

    for (int l = 0; l < 3; ++l) {
        int Kpad = (l == 0) ? KPAD_S : KPAD_BIG;
        int nP = V * (Kpad / 4);
        int nB = NCONV * (Kpad / 4);
        if (l == 0) {
            k_patch<3, KPAD_S><<<(nP + 255) / 256, 256>>>(bc_idx, bc_w, pPA);
            k_brot<3, KPAD_S><<<(nB + 255) / 256, 256>>>(Ws[l], pBB);
            dim3 g((NCONV + 127) / 128, (V + 127) / 128, 1);
            k_gemm<<<g, 256, SMEM_BYTES>>>(pPA, pBB, Bls[l], pConv,
                                           V, NCONV, Kpad, 0, 4);
            k_amp_bn<1><<<(V + 7) / 8, 256>>>(Bls[l], bng + l * TT, bnb + l * TT,
                                              bnm + l * TT, bnv + l * TT);
        } else {
            k_patch<TT, KPAD_BIG><<<(nP + 255) / 256, 256>>>(bc_idx, bc_w, pPA);
            k_brot<TT, KPAD_BIG><<<(nB + 255) / 256, 256>>>(Ws[l], pBB);
            dim3 g((NCONV + 127) / 128, (V + 127) / 128, 2);   // split-K x2
            k_gemm<<<g, 256, SMEM_BYTES>>>(pPA, pBB, Bls[l], pConv,
                                           V, NCONV, Kpad, 0, 63);
            k_amp_bn<2><<<(V + 7) / 8, 256>>>(Bls[l], bng + l * TT, bnb + l * TT,
                                              bnm + l * TT, bnv + l * TT);
        }
    }

    k_xpad<<<(V * 32 + 255) / 256, 256>>>();
    k_dwt<<<(V * 32 + 255) / 256, 256>>>(dw);
    dim3 g2((V + 127) / 128, (V + 127) / 128, 1);
    k_gemm<<<g2, 256, SMEM_BYTES>>>(pXX, pDD, db, out, V, V, KPAD_S, 1, 4);
}

// round 7
// speedup vs baseline: 4.9578x; 1.0434x over previous
#include <cuda_runtime.h>
#include <cuda_bf16.h>
#include <cstdint>

// ---------------------------------------------------------------------------
// IMCNN forward. HMMA m16n8k16 bf16, bf16x3 split, fp32 accum.
// R7: 4-warp CTAs with 64x64 warp tiles (smem crossbar traffic -33%,
//     MMA ILP per warp x2). Split-K x2 on big conv layers kept.
// ---------------------------------------------------------------------------

#define V      6890
#define RR     5
#define AA     8
#define TT     100
#define NCONV  800
#define KPAD_BIG 4032
#define KPAD_S   128
#define EPS_BN 1e-3f

__device__ float g_x[V * TT];
__device__ float g_conv[2 * V * NCONV];
__device__ __align__(16) __nv_bfloat16 g_pa[(size_t)V * 2 * KPAD_BIG];
__device__ __align__(16) __nv_bfloat16 g_bb[(size_t)NCONV * 2 * KPAD_BIG];
__device__ __align__(16) __nv_bfloat16 g_xx[(size_t)V * 2 * KPAD_S];
__device__ __align__(16) __nv_bfloat16 g_dd[(size_t)V * 2 * KPAD_S];

// -------------------- PTX helpers --------------------
__device__ __forceinline__ uint32_t smem_u32(const void* p) {
    uint32_t a;
    asm("{ .reg .u64 t; cvta.to.shared.u64 t, %1; cvt.u32.u64 %0, t; }"
        : "=r"(a) : "l"(p));
    return a;
}
#define CP_ASYNC16(dst, src) \
    asm volatile("cp.async.cg.shared.global [%0], [%1], 16;" \
                 :: "r"(dst), "l"(src))
#define CP_COMMIT() asm volatile("cp.async.commit_group;" ::: "memory")
#define CP_WAIT1()  asm volatile("cp.async.wait_group 1;" ::: "memory")
#define CP_WAIT0()  asm volatile("cp.async.wait_group 0;" ::: "memory")

#define LDSM4(R, addr) \
    asm volatile("ldmatrix.sync.aligned.m8n8.x4.shared.b16 {%0,%1,%2,%3}, [%4];" \
        : "=r"((R)[0]), "=r"((R)[1]), "=r"((R)[2]), "=r"((R)[3]) : "r"(addr))

#define SWZ(o) ((o) ^ (((o) >> 3) & 0x70))

__device__ __forceinline__ void mma16816(float* c, const uint32_t* a,
                                         const uint32_t* b) {
    asm volatile(
        "mma.sync.aligned.m16n8k16.row.col.f32.bf16.bf16.f32 "
        "{%0,%1,%2,%3}, {%4,%5,%6,%7}, {%8,%9}, {%0,%1,%2,%3};"
        : "+f"(c[0]), "+f"(c[1]), "+f"(c[2]), "+f"(c[3])
        : "r"(a[0]), "r"(a[1]), "r"(a[2]), "r"(a[3]), "r"(b[0]), "r"(b[1]));
}

// -------------------- small kernels --------------------
__global__ void k_norm(const float* __restrict__ sig,
                       const float* __restrict__ mean,
                       const float* __restrict__ var) {
    int i = blockIdx.x * blockDim.x + threadIdx.x;
    if (i < V * 3) {
        int c = i % 3;
        g_x[i] = (sig[i] - mean[c]) / sqrtf(var[c]);
    }
}

__device__ __forceinline__ void store4(__nv_bfloat16* buf, size_t rowbase,
                                       int k0, const float* s) {
    int kb = k0 >> 4, pos = k0 & 15;
    __nv_bfloat16 hv[4], lv[4];
#pragma unroll
    for (int e = 0; e < 4; ++e) {
        hv[e] = __float2bfloat16_rn(s[e]);
        lv[e] = __float2bfloat16_rn(s[e] - __bfloat162float(hv[e]));
    }
    size_t base = rowbase + (size_t)(kb * 32 + pos);
    *(uint2*)(buf + base)      = *(const uint2*)hv;
    *(uint2*)(buf + base + 16) = *(const uint2*)lv;
}

template <int CIN, int KPAD>
__global__ void k_patch(const int* __restrict__ bc_idx,
                        const float* __restrict__ bc_w,
                        __nv_bfloat16* __restrict__ pa) {
    constexpr int QK = KPAD / 4;
    constexpr int K = RR * AA * CIN;
    int i = blockIdx.x * blockDim.x + threadIdx.x;
    if (i >= V * QK) return;
    int q = i % QK, v = i / QK;
    int k0 = q * 4;
    float s[4] = {0.f, 0.f, 0.f, 0.f};
    if (k0 < K) {
        if (CIN % 4 == 0) {
            int ra = k0 / CIN, c0 = k0 % CIN;
            const int*   id = bc_idx + ((size_t)v * (RR * AA) + ra) * 3;
            const float* w  = bc_w   + ((size_t)v * (RR * AA) + ra) * 3;
            int i0 = id[0] * CIN, i1 = id[1] * CIN, i2 = id[2] * CIN;
            float w0 = w[0], w1 = w[1], w2 = w[2];
#pragma unroll
            for (int e = 0; e < 4; ++e)
                s[e] = g_x[i0 + c0 + e] * w0 + g_x[i1 + c0 + e] * w1 +
                       g_x[i2 + c0 + e] * w2;
        } else {
#pragma unroll
            for (int e = 0; e < 4; ++e) {
                int k = k0 + e;
                if (k < K) {
                    int ra = k / CIN, c = k % CIN;
                    const int*   id = bc_idx + ((size_t)v * (RR * AA) + ra) * 3;
                    const float* w  = bc_w   + ((size_t)v * (RR * AA) + ra) * 3;
                    s[e] = g_x[id[0] * CIN + c] * w[0] +
                           g_x[id[1] * CIN + c] * w[1] +
                           g_x[id[2] * CIN + c] * w[2];
                }
            }
        }
    }
    store4(pa, (size_t)v * (2 * KPAD), k0, s);
}

template <int CIN, int KPAD>
__global__ void k_brot(const float* __restrict__ W,
                       __nv_bfloat16* __restrict__ bb) {
    constexpr int QK = KPAD / 4;
    constexpr int K = RR * AA * CIN;
    int i = blockIdx.x * blockDim.x + threadIdx.x;
    if (i >= NCONV * QK) return;
    int q = i % QK, col = i / QK;
    int k0 = q * 4;
    int t = col % TT, n = col / TT;
    float s[4] = {0.f, 0.f, 0.f, 0.f};
#pragma unroll
    for (int e = 0; e < 4; ++e) {
        int k = k0 + e;
        if (k < K) {
            int c = k % CIN, ra = k / CIN;
            int a = ra & (AA - 1), r = ra >> 3;
            int a2 = (a + n) & (AA - 1);
            s[e] = W[((t * RR + r) * AA + a2) * CIN + c];
        }
    }
    store4(bb, (size_t)col * (2 * KPAD), k0, s);
}

__global__ void k_xpad() {
    int i = blockIdx.x * blockDim.x + threadIdx.x;
    if (i >= V * 32) return;
    int v = i >> 5, k0 = (i & 31) * 4;
    float s[4];
#pragma unroll
    for (int e = 0; e < 4; ++e)
        s[e] = (k0 + e < TT) ? g_x[v * TT + k0 + e] : 0.f;
    store4(g_xx, (size_t)v * (2 * KPAD_S), k0, s);
}

__global__ void k_dwt(const float* __restrict__ dw) {
    int i = blockIdx.x * blockDim.x + threadIdx.x;
    if (i >= V * 32) return;
    int n = i >> 5, k0 = (i & 31) * 4;
    float s[4];
#pragma unroll
    for (int e = 0; e < 4; ++e)
        s[e] = (k0 + e < TT) ? dw[(size_t)(k0 + e) * V + n] : 0.f;
    store4(g_dd, (size_t)n * (2 * KPAD_S), k0, s);
}

template <int NP>
__global__ void k_amp_bn(const float* __restrict__ bias,
                         const float* __restrict__ gam,
                         const float* __restrict__ bet,
                         const float* __restrict__ mu,
                         const float* __restrict__ var) {
    int warp = (blockIdx.x * blockDim.x + threadIdx.x) / 32;
    int lane = threadIdx.x & 31;
    if (warp >= V) return;
    const float* r0 = g_conv + (size_t)warp * NCONV;
    const float* r1 = r0 + (size_t)V * NCONV;
    float best = -1.f;
    int bestn = 0;
#pragma unroll
    for (int n = 0; n < AA; ++n) {
        float s = 0.f;
        for (int t = lane; t < TT; t += 32) {
            float x = r0[n * TT + t];
            if (NP == 2) x += r1[n * TT + t];
            x = fmaxf(x + bias[t], 0.f);
            s += x * x;
        }
#pragma unroll
        for (int off = 16; off > 0; off >>= 1)
            s += __shfl_xor_sync(0xFFFFFFFFu, s, off);
        if (s > best) { best = s; bestn = n; }
    }
    for (int t = lane; t < TT; t += 32) {
        float x = r0[bestn * TT + t];
        if (NP == 2) x += r1[bestn * TT + t];
        x = fmaxf(x + bias[t], 0.f);
        g_x[warp * TT + t] = gam[t] * (x - mu[t]) * rsqrtf(var[t] + EPS_BN) + bet[t];
    }
}

// -------------------- HMMA GEMM: 4 warps, 64x64/warp, 3-stage --------------
#define STGB 32768
#define SMEM_BYTES (3 * STGB + 1024)

__device__ __forceinline__ void load_stage(
    uint32_t sm, const __nv_bfloat16* A2, const __nv_bfloat16* B2,
    int row0, int col0, int M, int N, size_t KP2, int chunk, int tid) {
#pragma unroll
    for (int tI = 0; tI < 2; ++tI) {
        const __nv_bfloat16* src = tI ? B2 : A2;
        int rb = tI ? col0 : row0;
        int rm = tI ? N : M;
#pragma unroll
        for (int it = 0; it < 8; ++it) {
            int idx = tid + it * 128;
            int row = idx >> 3, seg = idx & 7;
            int gr = rb + row;
            if (gr > rm - 1) gr = rm - 1;
            const void* g = src + (size_t)gr * KP2 + (size_t)chunk * 64 + seg * 8;
            uint32_t dst = sm + tI * 16384 + SWZ((uint32_t)(row * 128 + seg * 16));
            CP_ASYNC16(dst, g);
        }
    }
    CP_COMMIT();
}

// mode 0: raw partial to C + part*M*N. mode 1: C += bias[col] (dense head).
__global__ void __launch_bounds__(128, 2)
k_gemm(const __nv_bfloat16* __restrict__ A2, const __nv_bfloat16* __restrict__ B2,
       const float* __restrict__ bias, float* __restrict__ C,
       int M, int N, int Kpad, int mode, int chPer) {
    extern __shared__ char dsm[];
    uint32_t raw = smem_u32(dsm);
    uint32_t sbase = (raw + 1023u) & ~1023u;

    int tid = threadIdx.x, wid = tid >> 5, lane = tid & 31;
    int warp_m = wid & 1, warp_n = wid >> 1;     // 2 x 2 warps, 64x64 each
    int row0 = blockIdx.y * 128, col0 = blockIdx.x * 128;
    int part = blockIdx.z;
    int nchTot = Kpad >> 5;
    int kc0 = part * chPer;
    int kc1 = kc0 + chPer; if (kc1 > nchTot) kc1 = nchTot;
    float* Cp = C + (size_t)part * M * N;
    size_t KP2 = 2 * (size_t)Kpad;

    float acc[4][8][4];
#pragma unroll
    for (int i = 0; i < 4; ++i)
#pragma unroll
        for (int j = 0; j < 8; ++j)
#pragma unroll
            for (int q = 0; q < 4; ++q) acc[i][j][q] = 0.f;

    load_stage(sbase,        A2, B2, row0, col0, M, N, KP2, kc0, tid);
    load_stage(sbase + STGB, A2, B2, row0, col0, M, N, KP2, kc0 + 1, tid);

    int slot = 0;
    for (int c = kc0; c < kc1; ++c) {
        if (c + 1 < kc1) { CP_WAIT1(); } else { CP_WAIT0(); }
        __syncthreads();
        if (c + 2 < kc1) {
            int wslot = slot + 2; if (wslot >= 3) wslot -= 3;
            load_stage(sbase + wslot * STGB, A2, B2, row0, col0, M, N, KP2,
                       c + 2, tid);
        }
        uint32_t sa = sbase + slot * STGB;
        if (++slot == 3) slot = 0;

#pragma unroll
        for (int ks = 0; ks < 2; ++ks) {
            uint32_t ah[4][4], al[4][4], bh[4][4], bl[4][4];
#pragma unroll
            for (int mi = 0; mi < 4; ++mi) {
                int arow = warp_m * 64 + mi * 16 + (lane & 15);
                uint32_t off = (uint32_t)(arow * 128 + ks * 64 + ((lane >> 4) << 4));
                LDSM4(ah[mi], sa + SWZ(off));
                LDSM4(al[mi], sa + SWZ(off + 32));
            }
#pragma unroll
            for (int bi = 0; bi < 4; ++bi) {
                int m = lane >> 3;
                int brow = warp_n * 64 + bi * 16 + ((m >> 1) << 3) + (lane & 7);
                uint32_t off = (uint32_t)(brow * 128 + ks * 64 + ((m & 1) << 4));
                LDSM4(bh[bi], sa + 16384 + SWZ(off));
                LDSM4(bl[bi], sa + 16384 + SWZ(off + 32));
            }
            // pass-major: 32 independent MMAs between accumulator reuses
#pragma unroll
            for (int mi = 0; mi < 4; ++mi)
#pragma unroll
                for (int ni = 0; ni < 8; ++ni)
                    mma16816(acc[mi][ni], ah[mi], &bh[ni >> 1][(ni & 1) * 2]);
#pragma unroll
            for (int mi = 0; mi < 4; ++mi)
#pragma unroll
                for (int ni = 0; ni < 8; ++ni)
                    mma16816(acc[mi][ni], ah[mi], &bl[ni >> 1][(ni & 1) * 2]);
#pragma unroll
            for (int mi = 0; mi < 4; ++mi)
#pragma unroll
                for (int ni = 0; ni < 8; ++ni)
                    mma16816(acc[mi][ni], al[mi], &bh[ni >> 1][(ni & 1) * 2]);
        }
    }

    int rbase = row0 + warp_m * 64;
    int cbase = col0 + warp_n * 64;
#pragma unroll
    for (int mi = 0; mi < 4; ++mi)
#pragma unroll
        for (int ni = 0; ni < 8; ++ni) {
            int r = rbase + mi * 16 + (lane >> 2);
            int cc = cbase + ni * 8 + (lane & 3) * 2;
            if (cc < N) {
                float b0 = mode ? bias[cc] : 0.f;
                float b1 = mode ? bias[cc + 1] : 0.f;
                if (r < M)
                    *(float2*)&Cp[(size_t)r * N + cc] =
                        make_float2(acc[mi][ni][0] + b0, acc[mi][ni][1] + b1);
                if (r + 8 < M)
                    *(float2*)&Cp[(size_t)(r + 8) * N + cc] =
                        make_float2(acc[mi][ni][2] + b0, acc[mi][ni][3] + b1);
            }
        }
}

// -------------------- launch --------------------
extern "C" void kernel_launch(void* const* d_in, const int* in_sizes, int n_in,
                              void* d_out, int out_size) {
    const float* signal = (const float*)d_in[0];
    const int*   bc_idx = (const int*)d_in[1];
    const float* bc_w   = (const float*)d_in[2];
    const float* nmean  = (const float*)d_in[3];
    const float* nvar   = (const float*)d_in[4];
    const float* Ws[3]  = {(const float*)d_in[5], (const float*)d_in[7],
                           (const float*)d_in[9]};
    const float* Bls[3] = {(const float*)d_in[6], (const float*)d_in[8],
                           (const float*)d_in[10]};
    const float* bng = (const float*)d_in[11];
    const float* bnb = (const float*)d_in[12];
    const float* bnm = (const float*)d_in[13];
    const float* bnv = (const float*)d_in[14];
    const float* dw  = (const float*)d_in[15];
    const float* db  = (const float*)d_in[16];
    float* out = (float*)d_out;

    cudaFuncSetAttribute(k_gemm, cudaFuncAttributeMaxDynamicSharedMemorySize,
                         SMEM_BYTES);

    __nv_bfloat16 *pPA, *pBB, *pXX, *pDD;
    float *pConv;
    cudaGetSymbolAddress((void**)&pPA, g_pa);
    cudaGetSymbolAddress((void**)&pBB, g_bb);
    cudaGetSymbolAddress((void**)&pXX, g_xx);
    cudaGetSymbolAddress((void**)&pDD, g_dd);
    cudaGetSymbolAddress((void**)&pConv, g_conv);

    k_norm<<<(V * 3 + 255) / 256, 256>>>(signal, nmean, nvar);

    for (int l = 0; l < 3; ++l) {
        int Kpad = (l == 0) ? KPAD_S : KPAD_BIG;
        int nP = V * (Kpad / 4);
        int nB = NCONV * (Kpad / 4);
        if (l == 0) {
            k_patch<3, KPAD_S><<<(nP + 255) / 256, 256>>>(bc_idx, bc_w, pPA);
            k_brot<3, KPAD_S><<<(nB + 255) / 256, 256>>>(Ws[l], pBB);
            dim3 g((NCONV + 127) / 128, (V + 127) / 128, 1);
            k_gemm<<<g, 128, SMEM_BYTES>>>(pPA, pBB, Bls[l], pConv,
                                           V, NCONV, Kpad, 0, 4);
            k_amp_bn<1><<<(V + 7) / 8, 256>>>(Bls[l], bng + l * TT, bnb + l * TT,
                                              bnm + l * TT, bnv + l * TT);
        } else {
            k_patch<TT, KPAD_BIG><<<(nP + 255) / 256, 256>>>(bc_idx, bc_w, pPA);
            k_brot<TT, KPAD_BIG><<<(nB + 255) / 256, 256>>>(Ws[l], pBB);
            dim3 g((NCONV + 127) / 128, (V + 127) / 128, 2);
            k_gemm<<<g, 128, SMEM_BYTES>>>(pPA, pBB, Bls[l], pConv,
                                           V, NCONV, Kpad, 0, 63);
            k_amp_bn<2><<<(V + 7) / 8, 256>>>(Bls[l], bng + l * TT, bnb + l * TT,
                                              bnm + l * TT, bnv + l * TT);
        }
    }

    k_xpad<<<(V * 32 + 255) / 256, 256>>>();
    k_dwt<<<(V * 32 + 255) / 256, 256>>>(dw);
    dim3 g2((V + 127) / 128, (V + 127) / 128, 1);
    k_gemm<<<g2, 128, SMEM_BYTES>>>(pXX, pDD, db, out, V, V, KPAD_S, 1, 4);
}